// round 5
// baseline (speedup 1.0000x reference)
#include <cuda_runtime.h>
#include <math.h>
#include <stdint.h>

#define D_    1024
#define B_    4
#define T_    2048
#define M_TOTAL (B_*T_)   // 8192 rows
#define NPAIR (M_TOTAL/2) // 4096 complex-packed row pairs

#define CHUNK 128
#define WARM  128

// ---------------- device scratch ----------------
__device__ __align__(16) float  h_buf[(size_t)M_TOTAL * D_];  // 32 MB scan output
__device__ __align__(16) float2 Gspec_perm[D_];               // permuted G spectrum (/1024, *gate)
__device__ __align__(16) float2 w32c[16];                     // omega_32^m  (m=0..15)
__device__ __align__(16) float2 w1024c[32];                   // omega_1024^l (l=0..31)

// compile-time helpers
__host__ __device__ constexpr int br5(int x) {
    return ((x & 1) << 4) | ((x & 2) << 2) | (x & 4) | ((x & 8) >> 2) | ((x & 16) >> 4);
}
// twiddle constants for in-register FFT32 (omega_32^m = cos - i sin)
__device__ constexpr float W32R[16] = {
    1.0f, 0.98078528040323044f, 0.92387953251128674f, 0.83146961230254524f,
    0.70710678118654757f, 0.55557023301960229f, 0.38268343236508984f, 0.19509032201612833f,
    0.0f, -0.19509032201612819f, -0.38268343236508973f, -0.55557023301960196f,
    -0.70710678118654746f, -0.83146961230254524f, -0.92387953251128674f, -0.98078528040323044f };
__device__ constexpr float W32I[16] = {
    0.0f, -0.19509032201612825f, -0.38268343236508978f, -0.55557023301960218f,
    -0.70710678118654757f, -0.83146961230254524f, -0.92387953251128674f, -0.98078528040323044f,
    -1.0f, -0.98078528040323044f, -0.92387953251128674f, -0.83146961230254546f,
    -0.70710678118654757f, -0.55557023301960218f, -0.38268343236508989f, -0.19509032201612861f };

// ---------------------------------------------------------------------------
// init twiddle tables (double precision -> float)
// ---------------------------------------------------------------------------
__global__ void init_tw_kernel() {
    const int t = threadIdx.x;
    const double PI2 = 6.283185307179586476925286766559;
    if (t < 16) {
        double s, c; sincos(-PI2 * t / 32.0, &s, &c);
        w32c[t] = make_float2((float)c, (float)s);
    }
    if (t < 32) {
        double s, c; sincos(-PI2 * t / 1024.0, &s, &c);
        w1024c[t] = make_float2((float)c, (float)s);
    }
}

// ---------------------------------------------------------------------------
// Gspec_perm[pos(k)] = gate * BK[k] * conj(UK[k]) / 1024   (double-prec DFT)
// pos(k) = (k & 31)*32 + br5(k >> 5)   -- matches transform output layout.
// grid: 128 blocks x 256 threads = 1024 warps, warp per k.
// ---------------------------------------------------------------------------
__global__ void build_gspec_kernel(const float* __restrict__ bk,
                                   const float* __restrict__ uk,
                                   const float* __restrict__ gate) {
    const int k    = blockIdx.x * 8 + (threadIdx.x >> 5);
    const int lane = threadIdx.x & 31;
    const double PI2 = 6.283185307179586476925286766559;

    double brr = 0, bri = 0, urr = 0, uri = 0;
    #pragma unroll 4
    for (int i = 0; i < 32; ++i) {
        const int n = lane + 32 * i;
        const int m = (n * k) & (D_ - 1);
        double s, c; sincos(-PI2 * m / 1024.0, &s, &c);
        const double bv = (double)bk[n], uv = (double)uk[n];
        brr += c * bv; bri += s * bv;
        urr += c * uv; uri += s * uv;
    }
    #pragma unroll
    for (int o = 16; o; o >>= 1) {
        brr += __shfl_xor_sync(0xFFFFFFFFu, brr, o);
        bri += __shfl_xor_sync(0xFFFFFFFFu, bri, o);
        urr += __shfl_xor_sync(0xFFFFFFFFu, urr, o);
        uri += __shfl_xor_sync(0xFFFFFFFFu, uri, o);
    }
    if (lane == 0) {
        const double sc = (double)gate[0] / 1024.0;
        // B * conj(U)
        const double gr = (brr * urr + bri * uri) * sc;
        const double gi = (bri * urr - brr * uri) * sc;
        const int pos = (k & 31) * 32 + br5(k >> 5);
        Gspec_perm[pos] = make_float2((float)gr, (float)gi);
    }
}

// ---------------------------------------------------------------------------
// Windowed IIR scan along T (validated in R1/R3/R4)
// ---------------------------------------------------------------------------
__global__ void scan_kernel(const float* __restrict__ x,
                            const float* __restrict__ decay_p) {
    const int dim = blockIdx.x * blockDim.x + threadIdx.x;
    const int b   = blockIdx.z;
    const int t0  = blockIdx.y * CHUNK;
    const float d = 1.0f / (1.0f + expf(-decay_p[0]));

    float acc = 0.f;
    const float* xp;
    if (t0 > 0) {
        xp = x + ((size_t)(b * T_ + t0 - WARM)) * D_ + dim;
        #pragma unroll 8
        for (int t = 0; t < WARM; ++t) { acc = fmaf(acc, d, xp[0]); xp += D_; }
    } else {
        xp = x + ((size_t)(b * T_)) * D_ + dim;
    }
    float* hp = h_buf + ((size_t)(b * T_ + t0)) * D_ + dim;
    #pragma unroll 4
    for (int t = 0; t < CHUNK; ++t) {
        acc = fmaf(acc, d, xp[0]); xp += D_;
        hp[0] = acc; hp += D_;
    }
}

// ---------------------------------------------------------------------------
// Warp-level 1024-pt complex FFT (four-step 32x32).
// Input : lane l holds u[l + 32r] in reg r (natural).
// Output: reg p, lane l hold X[br5(p) + 32*br5(l)]   (bit-reversed both axes)
// ---------------------------------------------------------------------------
__device__ __forceinline__ void fft1024_warp(float zr[32], float zi[32],
                                             const int lane,
                                             const float2* __restrict__ w32s,
                                             const float2* __restrict__ w1024s) {
    // ---- step 1: per-lane DIF FFT32 over regs (natural in, bitrev reg out) ----
    #pragma unroll
    for (int s = 0; s < 5; ++s) {
        const int h = 16 >> s;
        #pragma unroll
        for (int b = 0; b < 32; b += 2 * h) {
            #pragma unroll
            for (int j = 0; j < 16; ++j) {
                if (j < h) {
                    const int p = b + j, q = p + h;
                    const float ur = zr[p], ui = zi[p];
                    const float vr = zr[q], vi = zi[q];
                    zr[p] = ur + vr; zi[p] = ui + vi;
                    const float tr = ur - vr, ti = ui - vi;
                    const int m = j << s;
                    const float wr = W32R[m], wi = W32I[m];
                    zr[q] = tr * wr - ti * wi;
                    zi[q] = tr * wi + ti * wr;
                }
            }
        }
    }
    // ---- step 2: twiddle omega_1024^(lane*k2); reg p holds k2 = br5(p) ----
    {
        const float2 w = w1024s[lane];
        float tr = 1.f, ti = 0.f;
        #pragma unroll
        for (int k2 = 0; k2 < 32; ++k2) {
            const int p = br5(k2);
            const float ar = zr[p], ai = zi[p];
            zr[p] = ar * tr - ai * ti;
            zi[p] = ar * ti + ai * tr;
            const float nr = tr * w.x - ti * w.y;
            ti = tr * w.y + ti * w.x; tr = nr;
        }
    }
    // ---- step 3: cross-lane DIF FFT32 per reg (bitrev lane out) ----
    #pragma unroll
    for (int s = 0; s < 5; ++s) {
        const int h = 16 >> s;
        const float2 T = w32s[(lane & (h - 1)) << s];
        const bool up = (lane & h) != 0;
        #pragma unroll
        for (int p = 0; p < 32; ++p) {
            const float pr = __shfl_xor_sync(0xFFFFFFFFu, zr[p], h);
            const float pi = __shfl_xor_sync(0xFFFFFFFFu, zi[p], h);
            const float sr = zr[p] + pr, si = zi[p] + pi;        // lower
            const float dr = pr - zr[p], di = pi - zi[p];        // (low - up) at upper
            const float mr = dr * T.x - di * T.y;
            const float mi = dr * T.y + di * T.x;
            zr[p] = up ? mr : sr;
            zi[p] = up ? mi : si;
        }
    }
}

// ---------------------------------------------------------------------------
// conv kernel: per warp, rows (2p, 2p+1) packed as complex; FFT -> *Gp -> IFFT
// out = x + result. 512 CTAs x 256 threads (8 warps).
// ---------------------------------------------------------------------------
#define SM_GP      0                         // 1024 float2 = 8192 B
#define SM_W32     8192                      // 128 B
#define SM_W1024   8320                      // 256 B
#define SM_BOUNCE  8576                      // 8 warps x 1056 float2 (33-pad)
#define SMEM_CONV  (SM_BOUNCE + 8*1056*8)    // 76160 B

__global__ void __launch_bounds__(256)
conv_kernel(const float* __restrict__ x, float* __restrict__ out) {
    extern __shared__ char smem[];
    float2* gp_s   = (float2*)(smem + SM_GP);
    float2* w32s   = (float2*)(smem + SM_W32);
    float2* w1024s = (float2*)(smem + SM_W1024);

    const int tid  = threadIdx.x;
    const int wid  = tid >> 5;
    const int lane = tid & 31;
    float2* bb = (float2*)(smem + SM_BOUNCE) + wid * 1056;

    for (int i = tid; i < D_; i += 256) gp_s[i] = Gspec_perm[i];
    if (tid < 16) w32s[tid]   = w32c[tid];
    if (tid < 32) w1024s[tid] = w1024c[tid];
    __syncthreads();

    const int pair = blockIdx.x * 8 + wid;
    const float* pa = h_buf + (size_t)(2 * pair) * D_;
    const float* pb = pa + D_;

    float zr[32], zi[32];
    #pragma unroll
    for (int r = 0; r < 32; ++r) {
        zr[r] = pa[lane + 32 * r];
        zi[r] = pb[lane + 32 * r];
    }

    // forward
    fft1024_warp(zr, zi, lane, w32s, w1024s);

    // multiply by Gp, store conj to bounce (prep for inverse-via-conj)
    const int brl = __brev((unsigned)lane) >> 27;
    #pragma unroll
    for (int k2 = 0; k2 < 32; ++k2) {
        const int p = br5(k2);
        const float2 g = gp_s[k2 * 32 + lane];
        const float vr = zr[p] * g.x - zi[p] * g.y;
        const float vi = zr[p] * g.y + zi[p] * g.x;
        bb[k2 * 33 + brl] = make_float2(vr, -vi);
    }
    __syncwarp();

    // reload natural-time order for inverse transform
    #pragma unroll
    for (int r = 0; r < 32; ++r) {
        const float2 t = bb[lane * 33 + r];
        zr[r] = t.x; zi[r] = t.y;
    }
    __syncwarp();   // all reads done before overwrite below

    // inverse = conj(FFT(conj(V)))  (1/N folded into Gp)
    fft1024_warp(zr, zi, lane, w32s, w1024s);

    #pragma unroll
    for (int k2 = 0; k2 < 32; ++k2) {
        const int p = br5(k2);
        bb[k2 * 33 + brl] = make_float2(zr[p], -zi[p]);   // v[n], n = k2 + 32*br(lane)
    }
    __syncwarp();

    // epilogue: out = x + v (Re -> rowA, Im -> rowB), coalesced
    const float* xa = x + (size_t)(2 * pair) * D_;
    const float* xb = xa + D_;
    float* oa = out + (size_t)(2 * pair) * D_;
    float* ob = oa + D_;
    #pragma unroll
    for (int j = 0; j < 32; ++j) {
        const float2 v = bb[lane * 33 + j];
        const int n = 32 * j + lane;
        oa[n] = xa[n] + v.x;
        ob[n] = xb[n] + v.y;
    }
}

// ---------------------------------------------------------------------------
extern "C" void kernel_launch(void* const* d_in, const int* in_sizes, int n_in,
                              void* d_out, int out_size) {
    const float* x     = (const float*)d_in[0];
    const float* bk    = (const float*)d_in[1];
    const float* uk    = (const float*)d_in[2];
    const float* gate  = (const float*)d_in[3];
    const float* decay = (const float*)d_in[4];
    float* out = (float*)d_out;

    static int smem_set = 0;
    if (!smem_set) {
        cudaFuncSetAttribute(conv_kernel, cudaFuncAttributeMaxDynamicSharedMemorySize,
                             SMEM_CONV);
        smem_set = 1;
    }

    init_tw_kernel<<<1, 32>>>();
    build_gspec_kernel<<<128, 256>>>(bk, uk, gate);

    dim3 sgrid(D_ / 256, T_ / CHUNK, B_);
    scan_kernel<<<sgrid, 256>>>(x, decay);

    conv_kernel<<<NPAIR / 8, 256, SMEM_CONV>>>(x, out);
}

// round 6
// speedup vs baseline: 1.9607x; 1.9607x over previous
#include <cuda_runtime.h>
#include <math.h>
#include <stdint.h>

#define D_    1024
#define B_    4
#define T_    2048
#define M_TOTAL (B_*T_)   // 8192 rows
#define NPAIR (M_TOTAL/2) // 4096 complex-packed row pairs

#define CHUNK 128
#define WARM  128

// ---------------- device scratch ----------------
__device__ __align__(16) float  h_buf[(size_t)M_TOTAL * D_];  // 32 MB scan output
__device__ __align__(16) float2 Gspec_perm[D_];               // permuted G spectrum (/1024, *gate)
__device__ __align__(16) float2 w32c[16];                     // omega_32^m  (m=0..15)
__device__ __align__(16) float2 w1024c[32];                   // omega_1024^l (l=0..31)
__device__ __align__(16) float2 w1024_full[D_];               // omega_1024^m full table

// compile-time helpers
__host__ __device__ constexpr int br5(int x) {
    return ((x & 1) << 4) | ((x & 2) << 2) | (x & 4) | ((x & 8) >> 2) | ((x & 16) >> 4);
}
// twiddle constants for in-register FFT32 (omega_32^m = cos - i sin)
__device__ constexpr float W32R[16] = {
    1.0f, 0.98078528040323044f, 0.92387953251128674f, 0.83146961230254524f,
    0.70710678118654757f, 0.55557023301960229f, 0.38268343236508984f, 0.19509032201612833f,
    0.0f, -0.19509032201612819f, -0.38268343236508973f, -0.55557023301960196f,
    -0.70710678118654746f, -0.83146961230254524f, -0.92387953251128674f, -0.98078528040323044f };
__device__ constexpr float W32I[16] = {
    0.0f, -0.19509032201612825f, -0.38268343236508978f, -0.55557023301960218f,
    -0.70710678118654757f, -0.83146961230254524f, -0.92387953251128674f, -0.98078528040323044f,
    -1.0f, -0.98078528040323044f, -0.92387953251128674f, -0.83146961230254546f,
    -0.70710678118654757f, -0.55557023301960218f, -0.38268343236508989f, -0.19509032201612861f };

// ---------------------------------------------------------------------------
// init twiddle tables (double precision -> float), spread over 32 blocks so
// the fp64 sincos (B300 fp64 is ~2 ops/cyc/SM) never serializes on one SM.
// ---------------------------------------------------------------------------
__global__ void init_tw_kernel() {
    const int t = blockIdx.x * 32 + threadIdx.x;   // 0..1023
    const double PI2 = 6.283185307179586476925286766559;
    double s, c;
    sincos(-PI2 * t / 1024.0, &s, &c);
    w1024_full[t] = make_float2((float)c, (float)s);
    if (t < 16) {
        double s2, c2; sincos(-PI2 * t / 32.0, &s2, &c2);
        w32c[t] = make_float2((float)c2, (float)s2);
    }
    if (t < 32) w1024c[t] = make_float2((float)c, (float)s);
}

// ---------------------------------------------------------------------------
// Gspec_perm[pos(k)] = gate * BK[k] * conj(UK[k]) / 1024  (fp32 table DFT)
// pos(k) = (k & 31)*32 + br5(k >> 5). 128 blocks x 256 threads, warp per k.
// ---------------------------------------------------------------------------
__global__ void build_gspec_kernel(const float* __restrict__ bk,
                                   const float* __restrict__ uk,
                                   const float* __restrict__ gate) {
    __shared__ float  sbk[D_];
    __shared__ float  suk[D_];
    __shared__ float2 stw[D_];
    const int tid  = threadIdx.x;
    const int lane = tid & 31;
    const int k    = blockIdx.x * 8 + (tid >> 5);

    for (int i = tid; i < D_; i += 256) {
        sbk[i] = bk[i];
        suk[i] = uk[i];
        stw[i] = w1024_full[i];
    }
    __syncthreads();

    float brr = 0.f, bri = 0.f, urr = 0.f, uri = 0.f;
    #pragma unroll 8
    for (int i = 0; i < 32; ++i) {
        const int n = lane + 32 * i;
        const float2 w = stw[(n * k) & (D_ - 1)];
        const float bv = sbk[n], uv = suk[n];
        brr = fmaf(w.x, bv, brr); bri = fmaf(w.y, bv, bri);
        urr = fmaf(w.x, uv, urr); uri = fmaf(w.y, uv, uri);
    }
    #pragma unroll
    for (int o = 16; o; o >>= 1) {
        brr += __shfl_xor_sync(0xFFFFFFFFu, brr, o);
        bri += __shfl_xor_sync(0xFFFFFFFFu, bri, o);
        urr += __shfl_xor_sync(0xFFFFFFFFu, urr, o);
        uri += __shfl_xor_sync(0xFFFFFFFFu, uri, o);
    }
    if (lane == 0) {
        const float sc = gate[0] * (1.0f / 1024.0f);
        const float gr = (brr * urr + bri * uri) * sc;   // B * conj(U)
        const float gi = (bri * urr - brr * uri) * sc;
        const int pos = (k & 31) * 32 + br5(k >> 5);
        Gspec_perm[pos] = make_float2(gr, gi);
    }
}

// ---------------------------------------------------------------------------
// Windowed IIR scan along T (validated R1/R3/R4/R5)
// ---------------------------------------------------------------------------
__global__ void scan_kernel(const float* __restrict__ x,
                            const float* __restrict__ decay_p) {
    const int dim = blockIdx.x * blockDim.x + threadIdx.x;
    const int b   = blockIdx.z;
    const int t0  = blockIdx.y * CHUNK;
    const float d = 1.0f / (1.0f + expf(-decay_p[0]));

    float acc = 0.f;
    const float* xp;
    if (t0 > 0) {
        xp = x + ((size_t)(b * T_ + t0 - WARM)) * D_ + dim;
        #pragma unroll 8
        for (int t = 0; t < WARM; ++t) { acc = fmaf(acc, d, xp[0]); xp += D_; }
    } else {
        xp = x + ((size_t)(b * T_)) * D_ + dim;
    }
    float* hp = h_buf + ((size_t)(b * T_ + t0)) * D_ + dim;
    #pragma unroll 4
    for (int t = 0; t < CHUNK; ++t) {
        acc = fmaf(acc, d, xp[0]); xp += D_;
        hp[0] = acc; hp += D_;
    }
}

// ---------------------------------------------------------------------------
// Warp-level 1024-pt complex FFT (four-step 32x32), validated in R5.
// ---------------------------------------------------------------------------
__device__ __forceinline__ void fft1024_warp(float zr[32], float zi[32],
                                             const int lane,
                                             const float2* __restrict__ w32s,
                                             const float2* __restrict__ w1024s) {
    #pragma unroll
    for (int s = 0; s < 5; ++s) {
        const int h = 16 >> s;
        #pragma unroll
        for (int b = 0; b < 32; b += 2 * h) {
            #pragma unroll
            for (int j = 0; j < 16; ++j) {
                if (j < h) {
                    const int p = b + j, q = p + h;
                    const float ur = zr[p], ui = zi[p];
                    const float vr = zr[q], vi = zi[q];
                    zr[p] = ur + vr; zi[p] = ui + vi;
                    const float tr = ur - vr, ti = ui - vi;
                    const int m = j << s;
                    const float wr = W32R[m], wi = W32I[m];
                    zr[q] = tr * wr - ti * wi;
                    zi[q] = tr * wi + ti * wr;
                }
            }
        }
    }
    {
        const float2 w = w1024s[lane];
        float tr = 1.f, ti = 0.f;
        #pragma unroll
        for (int k2 = 0; k2 < 32; ++k2) {
            const int p = br5(k2);
            const float ar = zr[p], ai = zi[p];
            zr[p] = ar * tr - ai * ti;
            zi[p] = ar * ti + ai * tr;
            const float nr = tr * w.x - ti * w.y;
            ti = tr * w.y + ti * w.x; tr = nr;
        }
    }
    #pragma unroll
    for (int s = 0; s < 5; ++s) {
        const int h = 16 >> s;
        const float2 T = w32s[(lane & (h - 1)) << s];
        const bool up = (lane & h) != 0;
        #pragma unroll
        for (int p = 0; p < 32; ++p) {
            const float pr = __shfl_xor_sync(0xFFFFFFFFu, zr[p], h);
            const float pi = __shfl_xor_sync(0xFFFFFFFFu, zi[p], h);
            const float sr = zr[p] + pr, si = zi[p] + pi;
            const float dr = pr - zr[p], di = pi - zi[p];
            const float mr = dr * T.x - di * T.y;
            const float mi = dr * T.y + di * T.x;
            zr[p] = up ? mr : sr;
            zi[p] = up ? mi : si;
        }
    }
}

// ---------------------------------------------------------------------------
// conv kernel: per warp, rows (2p, 2p+1) packed as complex; FFT -> *Gp -> IFFT
// ---------------------------------------------------------------------------
#define SM_GP      0                         // 1024 float2 = 8192 B
#define SM_W32     8192                      // 128 B
#define SM_W1024   8320                      // 256 B
#define SM_BOUNCE  8576                      // 8 warps x 1056 float2 (33-pad)
#define SMEM_CONV  (SM_BOUNCE + 8*1056*8)    // 76160 B

__global__ void __launch_bounds__(256)
conv_kernel(const float* __restrict__ x, float* __restrict__ out) {
    extern __shared__ char smem[];
    float2* gp_s   = (float2*)(smem + SM_GP);
    float2* w32s   = (float2*)(smem + SM_W32);
    float2* w1024s = (float2*)(smem + SM_W1024);

    const int tid  = threadIdx.x;
    const int wid  = tid >> 5;
    const int lane = tid & 31;
    float2* bb = (float2*)(smem + SM_BOUNCE) + wid * 1056;

    for (int i = tid; i < D_; i += 256) gp_s[i] = Gspec_perm[i];
    if (tid < 16) w32s[tid]   = w32c[tid];
    if (tid < 32) w1024s[tid] = w1024c[tid];
    __syncthreads();

    const int pair = blockIdx.x * 8 + wid;
    const float* pa = h_buf + (size_t)(2 * pair) * D_;
    const float* pb = pa + D_;

    float zr[32], zi[32];
    #pragma unroll
    for (int r = 0; r < 32; ++r) {
        zr[r] = pa[lane + 32 * r];
        zi[r] = pb[lane + 32 * r];
    }

    fft1024_warp(zr, zi, lane, w32s, w1024s);

    const int brl = __brev((unsigned)lane) >> 27;
    #pragma unroll
    for (int k2 = 0; k2 < 32; ++k2) {
        const int p = br5(k2);
        const float2 g = gp_s[k2 * 32 + lane];
        const float vr = zr[p] * g.x - zi[p] * g.y;
        const float vi = zr[p] * g.y + zi[p] * g.x;
        bb[k2 * 33 + brl] = make_float2(vr, -vi);
    }
    __syncwarp();

    #pragma unroll
    for (int r = 0; r < 32; ++r) {
        const float2 t = bb[lane * 33 + r];
        zr[r] = t.x; zi[r] = t.y;
    }
    __syncwarp();

    fft1024_warp(zr, zi, lane, w32s, w1024s);

    #pragma unroll
    for (int k2 = 0; k2 < 32; ++k2) {
        const int p = br5(k2);
        bb[k2 * 33 + brl] = make_float2(zr[p], -zi[p]);
    }
    __syncwarp();

    const float* xa = x + (size_t)(2 * pair) * D_;
    const float* xb = xa + D_;
    float* oa = out + (size_t)(2 * pair) * D_;
    float* ob = oa + D_;
    #pragma unroll
    for (int j = 0; j < 32; ++j) {
        const float2 v = bb[lane * 33 + j];
        const int n = 32 * j + lane;
        oa[n] = xa[n] + v.x;
        ob[n] = xb[n] + v.y;
    }
}

// ---------------------------------------------------------------------------
extern "C" void kernel_launch(void* const* d_in, const int* in_sizes, int n_in,
                              void* d_out, int out_size) {
    const float* x     = (const float*)d_in[0];
    const float* bk    = (const float*)d_in[1];
    const float* uk    = (const float*)d_in[2];
    const float* gate  = (const float*)d_in[3];
    const float* decay = (const float*)d_in[4];
    float* out = (float*)d_out;

    static int smem_set = 0;
    if (!smem_set) {
        cudaFuncSetAttribute(conv_kernel, cudaFuncAttributeMaxDynamicSharedMemorySize,
                             SMEM_CONV);
        smem_set = 1;
    }

    init_tw_kernel<<<32, 32>>>();
    build_gspec_kernel<<<128, 256>>>(bk, uk, gate);

    dim3 sgrid(D_ / 256, T_ / CHUNK, B_);
    scan_kernel<<<sgrid, 256>>>(x, decay);

    conv_kernel<<<NPAIR / 8, 256, SMEM_CONV>>>(x, out);
}

// round 7
// speedup vs baseline: 2.6785x; 1.3661x over previous
#include <cuda_runtime.h>
#include <math.h>
#include <stdint.h>

#define D_    1024
#define B_    4
#define T_    2048
#define M_TOTAL (B_*T_)   // 8192 rows
#define NPAIR (M_TOTAL/2) // 4096 complex-packed row pairs

#define CHUNK 128
#define WARM  64          // d^64 ~ 3e-10: exact to fp32

// ---------------- device scratch ----------------
__device__ __align__(16) float  h_buf[(size_t)M_TOTAL * D_];  // 32 MB scan output
__device__ __align__(16) float2 Gspec_perm[D_];               // permuted G spectrum
__device__ __align__(16) float2 w1024_full[D_];               // omega_1024^m table

__host__ __device__ constexpr int br5(int x) {
    return ((x & 1) << 4) | ((x & 2) << 2) | (x & 4) | ((x & 8) >> 2) | ((x & 16) >> 4);
}
// omega_32^m (m=0..15), exact-to-fp32 constants
__device__ constexpr float W32R[16] = {
    1.0f, 0.98078528040323044f, 0.92387953251128674f, 0.83146961230254524f,
    0.70710678118654757f, 0.55557023301960229f, 0.38268343236508984f, 0.19509032201612833f,
    0.0f, -0.19509032201612819f, -0.38268343236508973f, -0.55557023301960196f,
    -0.70710678118654746f, -0.83146961230254524f, -0.92387953251128674f, -0.98078528040323044f };
__device__ constexpr float W32I[16] = {
    0.0f, -0.19509032201612825f, -0.38268343236508978f, -0.55557023301960218f,
    -0.70710678118654757f, -0.83146961230254524f, -0.92387953251128674f, -0.98078528040323044f,
    -1.0f, -0.98078528040323044f, -0.92387953251128674f, -0.83146961230254546f,
    -0.70710678118654757f, -0.55557023301960218f, -0.38268343236508989f, -0.19509032201612861f };

// ---------------------------------------------------------------------------
__global__ void init_tw_kernel() {
    const int t = blockIdx.x * 32 + threadIdx.x;   // 0..1023
    const double PI2 = 6.283185307179586476925286766559;
    double s, c;
    sincos(-PI2 * t / 1024.0, &s, &c);
    w1024_full[t] = make_float2((float)c, (float)s);
}

// ---------------------------------------------------------------------------
// Gspec_perm[pos(k)] = gate * BK[k] * conj(UK[k]) / 1024  (fp32 table DFT)
// New layout for register-FFT output: pos(k) = br5(k>>5)*32 + (k&31).
// ---------------------------------------------------------------------------
__global__ void build_gspec_kernel(const float* __restrict__ bk,
                                   const float* __restrict__ uk,
                                   const float* __restrict__ gate) {
    __shared__ float  sbk[D_];
    __shared__ float  suk[D_];
    __shared__ float2 stw[D_];
    const int tid  = threadIdx.x;
    const int lane = tid & 31;
    const int k    = blockIdx.x * 8 + (tid >> 5);

    for (int i = tid; i < D_; i += 256) {
        sbk[i] = bk[i];
        suk[i] = uk[i];
        stw[i] = w1024_full[i];
    }
    __syncthreads();

    float brr = 0.f, bri = 0.f, urr = 0.f, uri = 0.f;
    #pragma unroll 8
    for (int i = 0; i < 32; ++i) {
        const int n = lane + 32 * i;
        const float2 w = stw[(n * k) & (D_ - 1)];
        const float bv = sbk[n], uv = suk[n];
        brr = fmaf(w.x, bv, brr); bri = fmaf(w.y, bv, bri);
        urr = fmaf(w.x, uv, urr); uri = fmaf(w.y, uv, uri);
    }
    #pragma unroll
    for (int o = 16; o; o >>= 1) {
        brr += __shfl_xor_sync(0xFFFFFFFFu, brr, o);
        bri += __shfl_xor_sync(0xFFFFFFFFu, bri, o);
        urr += __shfl_xor_sync(0xFFFFFFFFu, urr, o);
        uri += __shfl_xor_sync(0xFFFFFFFFu, uri, o);
    }
    if (lane == 0) {
        const float sc = gate[0] * (1.0f / 1024.0f);
        const float gr = (brr * urr + bri * uri) * sc;   // B * conj(U)
        const float gi = (bri * urr - brr * uri) * sc;
        const int pos = br5(k >> 5) * 32 + (k & 31);
        Gspec_perm[pos] = make_float2(gr, gi);
    }
}

// ---------------------------------------------------------------------------
// Windowed IIR scan along T
// ---------------------------------------------------------------------------
__global__ void scan_kernel(const float* __restrict__ x,
                            const float* __restrict__ decay_p) {
    const int dim = blockIdx.x * blockDim.x + threadIdx.x;
    const int b   = blockIdx.z;
    const int t0  = blockIdx.y * CHUNK;
    const float d = 1.0f / (1.0f + expf(-decay_p[0]));

    float acc = 0.f;
    const float* xp;
    if (t0 > 0) {
        xp = x + ((size_t)(b * T_ + t0 - WARM)) * D_ + dim;
        #pragma unroll 8
        for (int t = 0; t < WARM; ++t) { acc = fmaf(acc, d, xp[0]); xp += D_; }
    } else {
        xp = x + ((size_t)(b * T_)) * D_ + dim;
    }
    float* hp = h_buf + ((size_t)(b * T_ + t0)) * D_ + dim;
    #pragma unroll 4
    for (int t = 0; t < CHUNK; ++t) {
        acc = fmaf(acc, d, xp[0]); xp += D_;
        hp[0] = acc; hp += D_;
    }
}

// ---------------------------------------------------------------------------
// In-register DIF FFT32 (natural in; reg p holds bin br5(p) out). Proven R5.
// ---------------------------------------------------------------------------
__device__ __forceinline__ void fft32_reg(float zr[32], float zi[32]) {
    #pragma unroll
    for (int s = 0; s < 5; ++s) {
        const int h = 16 >> s;
        #pragma unroll
        for (int b = 0; b < 32; b += 2 * h) {
            #pragma unroll
            for (int j = 0; j < 16; ++j) {
                if (j < h) {
                    const int p = b + j, q = p + h;
                    const float ur = zr[p], ui = zi[p];
                    const float vr = zr[q], vi = zi[q];
                    zr[p] = ur + vr; zi[p] = ui + vi;
                    const float tr = ur - vr, ti = ui - vi;
                    const int m = j << s;
                    const float wr = W32R[m], wi = W32I[m];
                    zr[q] = tr * wr - ti * wi;
                    zi[q] = tr * wi + ti * wr;
                }
            }
        }
    }
}

// twiddle omega_1024^(lane*k2) applied at reg br5(k2); 4 independent chains
__device__ __forceinline__ void twiddle1024(float zr[32], float zi[32], int lane) {
    const float2 w1 = __ldg(&w1024_full[lane]);
    const float w2r = w1.x * w1.x - w1.y * w1.y, w2i = 2.f * w1.x * w1.y;
    const float w3r = w2r * w1.x - w2i * w1.y,  w3i = w2r * w1.y + w2i * w1.x;
    const float w4r = w2r * w2r - w2i * w2i,    w4i = 2.f * w2r * w2i;
    float cr[4] = {1.f, w1.x, w2r, w3r};
    float ci[4] = {0.f, w1.y, w2i, w3i};
    #pragma unroll
    for (int j = 0; j < 8; ++j) {
        #pragma unroll
        for (int r = 0; r < 4; ++r) {
            const int p = br5(4 * j + r);
            const float ar = zr[p], ai = zi[p];
            zr[p] = ar * cr[r] - ai * ci[r];
            zi[p] = ar * ci[r] + ai * cr[r];
            const float nr = cr[r] * w4r - ci[r] * w4i;
            ci[r] = cr[r] * w4i + ci[r] * w4r;
            cr[r] = nr;
        }
    }
}

// padded smem transpose: reg p (bin br5(p)) x lane  ->  lane = bin, reg = old lane
__device__ __forceinline__ void transpose32(float2* bb, float zr[32], float zi[32], int lane) {
    __syncwarp();
    #pragma unroll
    for (int k2 = 0; k2 < 32; ++k2) {
        const int p = br5(k2);
        bb[k2 * 33 + lane] = make_float2(zr[p], zi[p]);
    }
    __syncwarp();
    #pragma unroll
    for (int r = 0; r < 32; ++r) {
        const float2 t = bb[lane * 33 + r];
        zr[r] = t.x; zi[r] = t.y;
    }
}

// full warp 1024-pt FFT (four-step, all-register butterflies, 1 smem bounce)
// in: lane=n&31, reg r=n>>5 (natural). out: lane=k&31, reg p holds k1=br5(p), k=lane+32*k1
__device__ __forceinline__ void fft1024(float2* bb, float zr[32], float zi[32], int lane) {
    fft32_reg(zr, zi);
    twiddle1024(zr, zi, lane);
    transpose32(bb, zr, zi, lane);
    fft32_reg(zr, zi);
}

// ---------------------------------------------------------------------------
// conv: rows (2p, 2p+1) packed as complex; fwd FFT -> *G(conj) -> inv FFT.
// 4 warps/CTA, static smem, no block sync. 1024 CTAs.
// ---------------------------------------------------------------------------
__global__ void __launch_bounds__(128, 5)
conv_kernel(const float* __restrict__ x, float* __restrict__ out) {
    __shared__ __align__(16) float2 bounce[4 * 1056];   // 33792 B

    const int wid  = threadIdx.x >> 5;
    const int lane = threadIdx.x & 31;
    float2* bb = bounce + wid * 1056;

    const int pair = blockIdx.x * 4 + wid;
    const float* pa = h_buf + (size_t)(2 * pair) * D_;
    const float* pb = pa + D_;

    float zr[32], zi[32];
    #pragma unroll
    for (int r = 0; r < 32; ++r) {
        zr[r] = pa[lane + 32 * r];
        zi[r] = pb[lane + 32 * r];
    }

    // forward FFT
    fft1024(bb, zr, zi, lane);

    // multiply by G (layout-matched) and conjugate (inverse via conj trick)
    #pragma unroll
    for (int p = 0; p < 32; ++p) {
        const float2 g = __ldg(&Gspec_perm[p * 32 + lane]);
        const float vr = zr[p] * g.x - zi[p] * g.y;
        const float vi = zr[p] * g.y + zi[p] * g.x;
        zr[p] = vr;
        zi[p] = -vi;
    }

    // reorder regs for inverse input: k>>5 = br5(p) -> swap p <-> br5(p) (free)
    #pragma unroll
    for (int p = 0; p < 32; ++p) {
        const int q = br5(p);
        if (p < q) {
            float t;
            t = zr[p]; zr[p] = zr[q]; zr[q] = t;
            t = zi[p]; zi[p] = zi[q]; zi[q] = t;
        }
    }

    // inverse = conj(FFT(conj(V))); 1/N folded into G
    fft1024(bb, zr, zi, lane);

    // epilogue: v[m], m = lane + 32*c at reg br5(c); Re->rowA, Im(-)->rowB
    const float* xa = x + (size_t)(2 * pair) * D_;
    const float* xb = xa + D_;
    float* oa = out + (size_t)(2 * pair) * D_;
    float* ob = oa + D_;
    #pragma unroll
    for (int c = 0; c < 32; ++c) {
        const int p = br5(c);
        const int m = lane + 32 * c;
        oa[m] = xa[m] + zr[p];
        ob[m] = xb[m] - zi[p];
    }
}

// ---------------------------------------------------------------------------
extern "C" void kernel_launch(void* const* d_in, const int* in_sizes, int n_in,
                              void* d_out, int out_size) {
    const float* x     = (const float*)d_in[0];
    const float* bk    = (const float*)d_in[1];
    const float* uk    = (const float*)d_in[2];
    const float* gate  = (const float*)d_in[3];
    const float* decay = (const float*)d_in[4];
    float* out = (float*)d_out;

    init_tw_kernel<<<32, 32>>>();
    build_gspec_kernel<<<128, 256>>>(bk, uk, gate);

    dim3 sgrid(D_ / 256, T_ / CHUNK, B_);
    scan_kernel<<<sgrid, 256>>>(x, decay);

    conv_kernel<<<NPAIR / 4, 128>>>(x, out);
}

// round 8
// speedup vs baseline: 3.5994x; 1.3438x over previous
#include <cuda_runtime.h>
#include <math.h>
#include <stdint.h>

#define D_    1024
#define B_    4
#define T_    2048
#define M_TOTAL (B_*T_)   // 8192 rows
#define NPAIR (M_TOTAL/2)

#define CCHUNK 128        // carry kernel T-chunk
#define WARM   64         // d^64 ~ 3e-10: exact to fp32

// ---------------- device scratch ----------------
__device__ __align__(16) float2 Gspec_perm[D_];              // permuted G spectrum
__device__ __align__(16) float  carry_buf[1025 * D_];        // h at 8-row boundaries (4.2 MB)

__host__ __device__ constexpr int br5(int x) {
    return ((x & 1) << 4) | ((x & 2) << 2) | (x & 4) | ((x & 8) >> 2) | ((x & 16) >> 4);
}
// omega_32^m (m=0..15), exact-to-fp32 constants
__device__ constexpr float W32R[16] = {
    1.0f, 0.98078528040323044f, 0.92387953251128674f, 0.83146961230254524f,
    0.70710678118654757f, 0.55557023301960229f, 0.38268343236508984f, 0.19509032201612833f,
    0.0f, -0.19509032201612819f, -0.38268343236508973f, -0.55557023301960196f,
    -0.70710678118654746f, -0.83146961230254524f, -0.92387953251128674f, -0.98078528040323044f };
__device__ constexpr float W32I[16] = {
    0.0f, -0.19509032201612825f, -0.38268343236508978f, -0.55557023301960218f,
    -0.70710678118654757f, -0.83146961230254524f, -0.92387953251128674f, -0.98078528040323044f,
    -1.0f, -0.98078528040323044f, -0.92387953251128674f, -0.83146961230254546f,
    -0.70710678118654757f, -0.55557023301960218f, -0.38268343236508989f, -0.19509032201612861f };

#define PI2F 6.2831853071795864769f

// ---------------------------------------------------------------------------
// Gspec_perm[pos(k)] = gate * BK[k] * conj(UK[k]) / 1024  (fp32 table DFT,
// twiddle table built in-CTA with sincosf). pos(k) = br5(k>>5)*32 + (k&31).
// ---------------------------------------------------------------------------
__global__ void build_gspec_kernel(const float* __restrict__ bk,
                                   const float* __restrict__ uk,
                                   const float* __restrict__ gate) {
    __shared__ float  sbk[D_];
    __shared__ float  suk[D_];
    __shared__ float2 stw[D_];
    const int tid  = threadIdx.x;
    const int lane = tid & 31;
    const int k    = blockIdx.x * 8 + (tid >> 5);

    for (int i = tid; i < D_; i += 256) {
        sbk[i] = bk[i];
        suk[i] = uk[i];
        float s, c;
        sincosf(-PI2F * (float)i * (1.0f / 1024.0f), &s, &c);
        stw[i] = make_float2(c, s);
    }
    __syncthreads();

    float brr = 0.f, bri = 0.f, urr = 0.f, uri = 0.f;
    #pragma unroll 8
    for (int i = 0; i < 32; ++i) {
        const int n = lane + 32 * i;
        const float2 w = stw[(n * k) & (D_ - 1)];
        const float bv = sbk[n], uv = suk[n];
        brr = fmaf(w.x, bv, brr); bri = fmaf(w.y, bv, bri);
        urr = fmaf(w.x, uv, urr); uri = fmaf(w.y, uv, uri);
    }
    #pragma unroll
    for (int o = 16; o; o >>= 1) {
        brr += __shfl_xor_sync(0xFFFFFFFFu, brr, o);
        bri += __shfl_xor_sync(0xFFFFFFFFu, bri, o);
        urr += __shfl_xor_sync(0xFFFFFFFFu, urr, o);
        uri += __shfl_xor_sync(0xFFFFFFFFu, uri, o);
    }
    if (lane == 0) {
        const float sc = gate[0] * (1.0f / 1024.0f);
        const float gr = (brr * urr + bri * uri) * sc;   // B * conj(U)
        const float gi = (bri * urr - brr * uri) * sc;
        const int pos = br5(k >> 5) * 32 + (k & 31);
        Gspec_perm[pos] = make_float2(gr, gi);
    }
}

// ---------------------------------------------------------------------------
// carry kernel: windowed IIR scan, emitting h only at 8-row boundaries.
// grid (T_/CCHUNK, B_) = 64 CTAs x 256 threads; thread owns float4 at d=tid*4.
// carry_buf[q] = h[8q-1]  (global row index).
// ---------------------------------------------------------------------------
__global__ void carry_kernel(const float* __restrict__ x,
                             const float* __restrict__ decay_p) {
    const int tid = threadIdx.x;
    const int b   = blockIdx.y;
    const int t0g = b * T_ + blockIdx.x * CCHUNK;      // global start row
    const float d = 1.0f / (1.0f + expf(-decay_p[0]));

    float4 acc = make_float4(0.f, 0.f, 0.f, 0.f);
    const float* xp;
    if (blockIdx.x > 0) {
        xp = x + (size_t)(t0g - WARM) * D_ + tid * 4;
        #pragma unroll 8
        for (int t = 0; t < WARM; ++t) {
            const float4 v = *reinterpret_cast<const float4*>(xp);
            acc.x = fmaf(acc.x, d, v.x); acc.y = fmaf(acc.y, d, v.y);
            acc.z = fmaf(acc.z, d, v.z); acc.w = fmaf(acc.w, d, v.w);
            xp += D_;
        }
    } else {
        xp = x + (size_t)t0g * D_ + tid * 4;
    }
    #pragma unroll 8
    for (int i = 0; i < CCHUNK; ++i) {
        const float4 v = *reinterpret_cast<const float4*>(xp);
        acc.x = fmaf(acc.x, d, v.x); acc.y = fmaf(acc.y, d, v.y);
        acc.z = fmaf(acc.z, d, v.z); acc.w = fmaf(acc.w, d, v.w);
        xp += D_;
        if ((i & 7) == 7) {
            const int q = (t0g + i + 1) >> 3;
            *reinterpret_cast<float4*>(&carry_buf[(size_t)q * D_ + tid * 4]) = acc;
        }
    }
}

// ---------------------------------------------------------------------------
// In-register DIF FFT32 (natural in; reg p holds bin br5(p) out). Proven R5-R7.
// ---------------------------------------------------------------------------
__device__ __forceinline__ void fft32_reg(float zr[32], float zi[32]) {
    #pragma unroll
    for (int s = 0; s < 5; ++s) {
        const int h = 16 >> s;
        #pragma unroll
        for (int b = 0; b < 32; b += 2 * h) {
            #pragma unroll
            for (int j = 0; j < 16; ++j) {
                if (j < h) {
                    const int p = b + j, q = p + h;
                    const float ur = zr[p], ui = zi[p];
                    const float vr = zr[q], vi = zi[q];
                    zr[p] = ur + vr; zi[p] = ui + vi;
                    const float tr = ur - vr, ti = ui - vi;
                    const int m = j << s;
                    const float wr = W32R[m], wi = W32I[m];
                    zr[q] = tr * wr - ti * wi;
                    zi[q] = tr * wi + ti * wr;
                }
            }
        }
    }
}

// twiddle omega_1024^(lane*k2) applied at reg br5(k2); 4 independent chains
__device__ __forceinline__ void twiddle1024(float zr[32], float zi[32],
                                            float w1x, float w1y) {
    const float w2r = w1x * w1x - w1y * w1y, w2i = 2.f * w1x * w1y;
    const float w3r = w2r * w1x - w2i * w1y, w3i = w2r * w1y + w2i * w1x;
    const float w4r = w2r * w2r - w2i * w2i, w4i = 2.f * w2r * w2i;
    float cr[4] = {1.f, w1x, w2r, w3r};
    float ci[4] = {0.f, w1y, w2i, w3i};
    #pragma unroll
    for (int j = 0; j < 8; ++j) {
        #pragma unroll
        for (int r = 0; r < 4; ++r) {
            const int p = br5(4 * j + r);
            const float ar = zr[p], ai = zi[p];
            zr[p] = ar * cr[r] - ai * ci[r];
            zi[p] = ar * ci[r] + ai * cr[r];
            const float nr = cr[r] * w4r - ci[r] * w4i;
            ci[r] = cr[r] * w4i + ci[r] * w4r;
            cr[r] = nr;
        }
    }
}

__device__ __forceinline__ void transpose32(float2* bb, float zr[32], float zi[32], int lane) {
    __syncwarp();
    #pragma unroll
    for (int k2 = 0; k2 < 32; ++k2) {
        const int p = br5(k2);
        bb[k2 * 33 + lane] = make_float2(zr[p], zi[p]);
    }
    __syncwarp();
    #pragma unroll
    for (int r = 0; r < 32; ++r) {
        const float2 t = bb[lane * 33 + r];
        zr[r] = t.x; zi[r] = t.y;
    }
}

__device__ __forceinline__ void fft1024(float2* bb, float zr[32], float zi[32],
                                        int lane, float w1x, float w1y) {
    fft32_reg(zr, zi);
    twiddle1024(zr, zi, w1x, w1y);
    transpose32(bb, zr, zi, lane);
    fft32_reg(zr, zi);
}

// ---------------------------------------------------------------------------
// Fused conv: CTA = 4 warps handles 8 consecutive rows (pairs 4q..4q+3).
// Phase 1: in-SMEM scan of the 8 h rows from x + carry.
// Phase 2: per-warp pair FFT -> *G(conj) -> inverse FFT -> residual.
// SMEM: sh (32 KB) aliases the 4x1056-float2 bounce region (33.8 KB).
// ---------------------------------------------------------------------------
__global__ void __launch_bounds__(128)
conv_kernel(const float* __restrict__ x, float* __restrict__ out,
            const float* __restrict__ decay_p) {
    __shared__ __align__(16) float2 bounce[4 * 1056];   // 33792 B (sh aliases it)
    float* sh = (float*)bounce;                         // 8 x 1024 floats

    const int tid  = threadIdx.x;
    const int wid  = tid >> 5;
    const int lane = tid & 31;
    const int q    = blockIdx.x;          // rows 8q .. 8q+7
    const int row0 = q * 8;
    float2* bb = bounce + wid * 1056;

    const float dcy = 1.0f / (1.0f + expf(-decay_p[0]));

    // ---- phase 1: scan 8 rows; thread owns cols [tid*4, +4) and [512+tid*4, +4)
    {
        float4 a0, a1;
        if ((row0 & (T_ - 1)) != 0) {
            a0 = *reinterpret_cast<const float4*>(&carry_buf[(size_t)q * D_ + tid * 4]);
            a1 = *reinterpret_cast<const float4*>(&carry_buf[(size_t)q * D_ + 512 + tid * 4]);
        } else {
            a0 = make_float4(0.f, 0.f, 0.f, 0.f);
            a1 = a0;
        }
        const float* xp = x + (size_t)row0 * D_ + tid * 4;
        #pragma unroll
        for (int r = 0; r < 8; ++r) {
            const float4 v0 = *reinterpret_cast<const float4*>(xp);
            const float4 v1 = *reinterpret_cast<const float4*>(xp + 512);
            a0.x = fmaf(a0.x, dcy, v0.x); a0.y = fmaf(a0.y, dcy, v0.y);
            a0.z = fmaf(a0.z, dcy, v0.z); a0.w = fmaf(a0.w, dcy, v0.w);
            a1.x = fmaf(a1.x, dcy, v1.x); a1.y = fmaf(a1.y, dcy, v1.y);
            a1.z = fmaf(a1.z, dcy, v1.z); a1.w = fmaf(a1.w, dcy, v1.w);
            *reinterpret_cast<float4*>(&sh[r * D_ + tid * 4])       = a0;
            *reinterpret_cast<float4*>(&sh[r * D_ + 512 + tid * 4]) = a1;
            xp += D_;
        }
    }
    __syncthreads();

    // ---- phase 2: load pair rows into registers ----
    float zr[32], zi[32];
    {
        const float* ra = sh + (2 * wid) * D_;
        const float* rb = ra + D_;
        #pragma unroll
        for (int r = 0; r < 32; ++r) {
            zr[r] = ra[lane + 32 * r];
            zi[r] = rb[lane + 32 * r];
        }
    }
    __syncthreads();   // sh fully consumed before bounce writes begin

    float w1x, w1y;
    sincosf(-PI2F * (float)lane * (1.0f / 1024.0f), &w1y, &w1x);   // s->w1y, c->w1x

    // forward FFT
    fft1024(bb, zr, zi, lane, w1x, w1y);

    // multiply by G (layout-matched) and conjugate (inverse via conj trick)
    #pragma unroll
    for (int p = 0; p < 32; ++p) {
        const float2 g = __ldg(&Gspec_perm[p * 32 + lane]);
        const float vr = zr[p] * g.x - zi[p] * g.y;
        const float vi = zr[p] * g.y + zi[p] * g.x;
        zr[p] = vr;
        zi[p] = -vi;
    }
    // reorder regs for inverse input (bit-reversal involution, free)
    #pragma unroll
    for (int p = 0; p < 32; ++p) {
        const int qq = br5(p);
        if (p < qq) {
            float t;
            t = zr[p]; zr[p] = zr[qq]; zr[qq] = t;
            t = zi[p]; zi[p] = zi[qq]; zi[qq] = t;
        }
    }
    // inverse = conj(FFT(conj(V))); 1/N folded into G
    fft1024(bb, zr, zi, lane, w1x, w1y);

    // ---- epilogue: out = x + v  (x rows L1/L2-hot from phase 1) ----
    const int pair = q * 4 + wid;
    const float* xa = x + (size_t)(2 * pair) * D_;
    const float* xb = xa + D_;
    float* oa = out + (size_t)(2 * pair) * D_;
    float* ob = oa + D_;
    #pragma unroll
    for (int c = 0; c < 32; ++c) {
        const int p = br5(c);
        const int m = lane + 32 * c;
        oa[m] = xa[m] + zr[p];
        ob[m] = xb[m] - zi[p];
    }
}

// ---------------------------------------------------------------------------
extern "C" void kernel_launch(void* const* d_in, const int* in_sizes, int n_in,
                              void* d_out, int out_size) {
    const float* x     = (const float*)d_in[0];
    const float* bk    = (const float*)d_in[1];
    const float* uk    = (const float*)d_in[2];
    const float* gate  = (const float*)d_in[3];
    const float* decay = (const float*)d_in[4];
    float* out = (float*)d_out;

    build_gspec_kernel<<<128, 256>>>(bk, uk, gate);

    dim3 cgrid(T_ / CCHUNK, B_);
    carry_kernel<<<cgrid, 256>>>(x, decay);

    conv_kernel<<<M_TOTAL / 8, 128>>>(x, out, decay);
}

// round 9
// speedup vs baseline: 3.6216x; 1.0062x over previous
#include <cuda_runtime.h>
#include <math.h>
#include <stdint.h>

#define D_    1024
#define B_    4
#define T_    2048
#define M_TOTAL (B_*T_)   // 8192 rows

#define CCHUNK 64         // carry kernel T-chunk
#define WARM   64         // d^64 ~ 3e-10: exact to fp32

// ---------------- device scratch ----------------
__device__ __align__(16) float2 Gspec_perm[D_];              // permuted G spectrum
__device__ __align__(16) float  carry_buf[1025 * D_];        // h at 8-row boundaries

__host__ __device__ constexpr int br5(int x) {
    return ((x & 1) << 4) | ((x & 2) << 2) | (x & 4) | ((x & 8) >> 2) | ((x & 16) >> 4);
}
// omega_32^m (m=0..15), exact-to-fp32 constants
__device__ constexpr float W32R[16] = {
    1.0f, 0.98078528040323044f, 0.92387953251128674f, 0.83146961230254524f,
    0.70710678118654757f, 0.55557023301960229f, 0.38268343236508984f, 0.19509032201612833f,
    0.0f, -0.19509032201612819f, -0.38268343236508973f, -0.55557023301960196f,
    -0.70710678118654746f, -0.83146961230254524f, -0.92387953251128674f, -0.98078528040323044f };
__device__ constexpr float W32I[16] = {
    0.0f, -0.19509032201612825f, -0.38268343236508978f, -0.55557023301960218f,
    -0.70710678118654757f, -0.83146961230254524f, -0.92387953251128674f, -0.98078528040323044f,
    -1.0f, -0.98078528040323044f, -0.92387953251128674f, -0.83146961230254546f,
    -0.70710678118654757f, -0.55557023301960218f, -0.38268343236508989f, -0.19509032201612861f };

#define PI2F 6.2831853071795864769f

// ---------------------------------------------------------------------------
// In-register DIF FFT32 (natural in; reg p holds bin br5(p) out). Proven R5-R8.
// ---------------------------------------------------------------------------
__device__ __forceinline__ void fft32_reg(float zr[32], float zi[32]) {
    #pragma unroll
    for (int s = 0; s < 5; ++s) {
        const int h = 16 >> s;
        #pragma unroll
        for (int b = 0; b < 32; b += 2 * h) {
            #pragma unroll
            for (int j = 0; j < 16; ++j) {
                if (j < h) {
                    const int p = b + j, q = p + h;
                    const float ur = zr[p], ui = zi[p];
                    const float vr = zr[q], vi = zi[q];
                    zr[p] = ur + vr; zi[p] = ui + vi;
                    const float tr = ur - vr, ti = ui - vi;
                    const int m = j << s;
                    const float wr = W32R[m], wi = W32I[m];
                    zr[q] = tr * wr - ti * wi;
                    zi[q] = tr * wi + ti * wr;
                }
            }
        }
    }
}

// twiddle omega_1024^(lane*k2) applied at reg br5(k2); 4 independent chains
__device__ __forceinline__ void twiddle1024(float zr[32], float zi[32],
                                            float w1x, float w1y) {
    const float w2r = w1x * w1x - w1y * w1y, w2i = 2.f * w1x * w1y;
    const float w3r = w2r * w1x - w2i * w1y, w3i = w2r * w1y + w2i * w1x;
    const float w4r = w2r * w2r - w2i * w2i, w4i = 2.f * w2r * w2i;
    float cr[4] = {1.f, w1x, w2r, w3r};
    float ci[4] = {0.f, w1y, w2i, w3i};
    #pragma unroll
    for (int j = 0; j < 8; ++j) {
        #pragma unroll
        for (int r = 0; r < 4; ++r) {
            const int p = br5(4 * j + r);
            const float ar = zr[p], ai = zi[p];
            zr[p] = ar * cr[r] - ai * ci[r];
            zi[p] = ar * ci[r] + ai * cr[r];
            const float nr = cr[r] * w4r - ci[r] * w4i;
            ci[r] = cr[r] * w4i + ci[r] * w4r;
            cr[r] = nr;
        }
    }
}

__device__ __forceinline__ void transpose32(float2* bb, float zr[32], float zi[32], int lane) {
    __syncwarp();
    #pragma unroll
    for (int k2 = 0; k2 < 32; ++k2) {
        const int p = br5(k2);
        bb[k2 * 33 + lane] = make_float2(zr[p], zi[p]);
    }
    __syncwarp();
    #pragma unroll
    for (int r = 0; r < 32; ++r) {
        const float2 t = bb[lane * 33 + r];
        zr[r] = t.x; zi[r] = t.y;
    }
}

// warp 1024-pt FFT. in: lane=n&31, reg=n>>5. out: Z[k] at lane=k&31, reg=br5(k>>5)
__device__ __forceinline__ void fft1024(float2* bb, float zr[32], float zi[32],
                                        int lane, float w1x, float w1y) {
    fft32_reg(zr, zi);
    twiddle1024(zr, zi, w1x, w1y);
    transpose32(bb, zr, zi, lane);
    fft32_reg(zr, zi);
}

// ---------------------------------------------------------------------------
// build G spectrum with ONE warp + ONE FFT:
//   Z = FFT(bk + i*uk); BK = (Z[k]+conj(Z[-k]))/2; UK = (Z[k]-conj(Z[-k]))/2i
//   Gspec_perm[br5(k>>5)*32 + (k&31)] = gate * BK * conj(UK) / 1024
// ---------------------------------------------------------------------------
__global__ void build_gspec_kernel(const float* __restrict__ bk,
                                   const float* __restrict__ uk,
                                   const float* __restrict__ gate) {
    __shared__ __align__(16) float2 bbs[1056];
    __shared__ float zsr[D_], zsi[D_];
    const int lane = threadIdx.x;   // 32 threads

    float zr[32], zi[32];
    #pragma unroll
    for (int r = 0; r < 32; ++r) {
        zr[r] = bk[lane + 32 * r];
        zi[r] = uk[lane + 32 * r];
    }
    float w1x, w1y;
    sincosf(-PI2F * (float)lane * (1.0f / 1024.0f), &w1y, &w1x);
    fft1024(bbs, zr, zi, lane, w1x, w1y);

    // scatter Z to natural order (separate re/im: conflict-free)
    #pragma unroll
    for (int p = 0; p < 32; ++p) {
        const int k = lane + 32 * br5(p);
        zsr[k] = zr[p]; zsi[k] = zi[p];
    }
    __syncwarp();

    const float sc = gate[0] * (1.0f / 1024.0f);
    #pragma unroll
    for (int j = 0; j < 32; ++j) {
        const int k  = 32 * j + lane;
        const int km = (D_ - k) & (D_ - 1);
        const float a = zsr[k],  b = zsi[k];
        const float c = zsr[km], d = zsi[km];
        const float bkr = 0.5f * (a + c), bki = 0.5f * (b - d);
        const float ukr = 0.5f * (b + d), uki = 0.5f * (c - a);
        const float gr = sc * (bkr * ukr + bki * uki);   // BK * conj(UK)
        const float gi = sc * (bki * ukr - bkr * uki);
        Gspec_perm[br5(j) * 32 + lane] = make_float2(gr, gi);
    }
}

// ---------------------------------------------------------------------------
// carry kernel: windowed IIR scan, emitting h only at 8-row boundaries.
// grid (T_/CCHUNK, B_) = 128 CTAs x 256 threads.
// ---------------------------------------------------------------------------
__global__ void carry_kernel(const float* __restrict__ x,
                             const float* __restrict__ decay_p) {
    const int tid = threadIdx.x;
    const int b   = blockIdx.y;
    const int t0g = b * T_ + blockIdx.x * CCHUNK;
    const float d = 1.0f / (1.0f + expf(-decay_p[0]));

    float4 acc = make_float4(0.f, 0.f, 0.f, 0.f);
    const float* xp;
    if (blockIdx.x > 0) {
        xp = x + (size_t)(t0g - WARM) * D_ + tid * 4;
        #pragma unroll 8
        for (int t = 0; t < WARM; ++t) {
            const float4 v = *reinterpret_cast<const float4*>(xp);
            acc.x = fmaf(acc.x, d, v.x); acc.y = fmaf(acc.y, d, v.y);
            acc.z = fmaf(acc.z, d, v.z); acc.w = fmaf(acc.w, d, v.w);
            xp += D_;
        }
    } else {
        xp = x + (size_t)t0g * D_ + tid * 4;
    }
    #pragma unroll 8
    for (int i = 0; i < CCHUNK; ++i) {
        const float4 v = *reinterpret_cast<const float4*>(xp);
        acc.x = fmaf(acc.x, d, v.x); acc.y = fmaf(acc.y, d, v.y);
        acc.z = fmaf(acc.z, d, v.z); acc.w = fmaf(acc.w, d, v.w);
        xp += D_;
        if ((i & 7) == 7) {
            const int q = (t0g + i + 1) >> 3;
            *reinterpret_cast<float4*>(&carry_buf[(size_t)q * D_ + tid * 4]) = acc;
        }
    }
}

// ---------------------------------------------------------------------------
// Fused conv (unchanged from passing R8): CTA = 4 warps, 8 rows.
// ---------------------------------------------------------------------------
__global__ void __launch_bounds__(128)
conv_kernel(const float* __restrict__ x, float* __restrict__ out,
            const float* __restrict__ decay_p) {
    __shared__ __align__(16) float2 bounce[4 * 1056];
    float* sh = (float*)bounce;

    const int tid  = threadIdx.x;
    const int wid  = tid >> 5;
    const int lane = tid & 31;
    const int q    = blockIdx.x;
    const int row0 = q * 8;
    float2* bb = bounce + wid * 1056;

    const float dcy = 1.0f / (1.0f + expf(-decay_p[0]));

    // phase 1: scan 8 rows into sh
    {
        float4 a0, a1;
        if ((row0 & (T_ - 1)) != 0) {
            a0 = *reinterpret_cast<const float4*>(&carry_buf[(size_t)q * D_ + tid * 4]);
            a1 = *reinterpret_cast<const float4*>(&carry_buf[(size_t)q * D_ + 512 + tid * 4]);
        } else {
            a0 = make_float4(0.f, 0.f, 0.f, 0.f);
            a1 = a0;
        }
        const float* xp = x + (size_t)row0 * D_ + tid * 4;
        #pragma unroll
        for (int r = 0; r < 8; ++r) {
            const float4 v0 = *reinterpret_cast<const float4*>(xp);
            const float4 v1 = *reinterpret_cast<const float4*>(xp + 512);
            a0.x = fmaf(a0.x, dcy, v0.x); a0.y = fmaf(a0.y, dcy, v0.y);
            a0.z = fmaf(a0.z, dcy, v0.z); a0.w = fmaf(a0.w, dcy, v0.w);
            a1.x = fmaf(a1.x, dcy, v1.x); a1.y = fmaf(a1.y, dcy, v1.y);
            a1.z = fmaf(a1.z, dcy, v1.z); a1.w = fmaf(a1.w, dcy, v1.w);
            *reinterpret_cast<float4*>(&sh[r * D_ + tid * 4])       = a0;
            *reinterpret_cast<float4*>(&sh[r * D_ + 512 + tid * 4]) = a1;
            xp += D_;
        }
    }
    __syncthreads();

    float zr[32], zi[32];
    {
        const float* ra = sh + (2 * wid) * D_;
        const float* rb = ra + D_;
        #pragma unroll
        for (int r = 0; r < 32; ++r) {
            zr[r] = ra[lane + 32 * r];
            zi[r] = rb[lane + 32 * r];
        }
    }
    __syncthreads();

    float w1x, w1y;
    sincosf(-PI2F * (float)lane * (1.0f / 1024.0f), &w1y, &w1x);

    fft1024(bb, zr, zi, lane, w1x, w1y);

    #pragma unroll
    for (int p = 0; p < 32; ++p) {
        const float2 g = __ldg(&Gspec_perm[p * 32 + lane]);
        const float vr = zr[p] * g.x - zi[p] * g.y;
        const float vi = zr[p] * g.y + zi[p] * g.x;
        zr[p] = vr;
        zi[p] = -vi;
    }
    #pragma unroll
    for (int p = 0; p < 32; ++p) {
        const int qq = br5(p);
        if (p < qq) {
            float t;
            t = zr[p]; zr[p] = zr[qq]; zr[qq] = t;
            t = zi[p]; zi[p] = zi[qq]; zi[qq] = t;
        }
    }
    fft1024(bb, zr, zi, lane, w1x, w1y);

    const int pair = q * 4 + wid;
    const float* xa = x + (size_t)(2 * pair) * D_;
    const float* xb = xa + D_;
    float* oa = out + (size_t)(2 * pair) * D_;
    float* ob = oa + D_;
    #pragma unroll
    for (int c = 0; c < 32; ++c) {
        const int p = br5(c);
        const int m = lane + 32 * c;
        oa[m] = xa[m] + zr[p];
        ob[m] = xb[m] - zi[p];
    }
}

// ---------------------------------------------------------------------------
extern "C" void kernel_launch(void* const* d_in, const int* in_sizes, int n_in,
                              void* d_out, int out_size) {
    const float* x     = (const float*)d_in[0];
    const float* bk    = (const float*)d_in[1];
    const float* uk    = (const float*)d_in[2];
    const float* gate  = (const float*)d_in[3];
    const float* decay = (const float*)d_in[4];
    float* out = (float*)d_out;

    build_gspec_kernel<<<1, 32>>>(bk, uk, gate);

    dim3 cgrid(T_ / CCHUNK, B_);
    carry_kernel<<<cgrid, 256>>>(x, decay);

    conv_kernel<<<M_TOTAL / 8, 128>>>(x, out, decay);
}